// round 8
// baseline (speedup 1.0000x reference)
#include <cuda_runtime.h>
#include <cstdint>

// embedding_bag(mode='mean'): B bags over a [V,64] fp32 table.
// One HALF-WARP per bag; sublane s (0..15) owns one float4 (cols 4s..4s+3).
// 16 lanes x 16B = one full 256B row per half-warp; each warp LDG.E.128
// fetches TWO rows (512B). Unroll x4 (2KB in flight per warp) + 2-wide tail.
// Row addresses are u32 BYTE offsets (V*256B = 256MB fits u32).
// Cache policy: indices are read-once -> ld.global.cs (streaming, don't
// pollute L2); output is write-once -> st.global.cs. Weight rows keep the
// default policy so duplicate rows can hit in L2.

static __device__ __forceinline__ long long ldcs_i64(const long long* p) {
    long long v;
    asm volatile("ld.global.cs.b64 %0, [%1];" : "=l"(v) : "l"(p));
    return v;
}
static __device__ __forceinline__ int ldcs_i32(const int* p) {
    int v;
    asm volatile("ld.global.cs.b32 %0, [%1];" : "=r"(v) : "l"(p));
    return v;
}
static __device__ __forceinline__ void stcs_f4(float4* p, float4 v) {
    asm volatile("st.global.cs.v4.f32 [%0], {%1,%2,%3,%4};"
                 :: "l"(p), "f"(v.x), "f"(v.y), "f"(v.z), "f"(v.w));
}

__global__ __launch_bounds__(256, 8)
void embag_mean_kernel(const void* __restrict__ indices_raw,
                       const void* __restrict__ offsets_raw,
                       const char* __restrict__ weight_bytes,
                       float* __restrict__ out,
                       int num_bags, long long total_indices) {
    const int warp_global = (int)((blockIdx.x * (unsigned)blockDim.x + threadIdx.x) >> 5);
    const int lane = threadIdx.x & 31;
    const int half = lane >> 4;        // bag within the warp
    const int sub  = lane & 15;        // float4 column group within the row
    const int bag  = 2 * warp_global + half;
    if (bag >= num_bags) return;

    const char* __restrict__ wbase = weight_bytes + (unsigned)(sub * 16);

    // Inline dtype detection (int64 vs int32 indices): ids < 2^31, so an
    // int64 LE buffer has every odd 32-bit word zero; an int32 buffer has
    // random nonzero ids there (P[all 4 zero] ~ 1e-24). Uniform result.
    const int* wprobe = (const int*)indices_raw;
    int allz = 1;
    #pragma unroll
    for (int k = 1; k < 9; k += 2) allz &= (__ldg(&wprobe[k]) == 0);
    const bool is64 = (allz != 0);

    const long long* __restrict__ idx64 = (const long long*)indices_raw;
    const int*       __restrict__ idx32 = (const int*)indices_raw;
    const long long* __restrict__ off64 = (const long long*)offsets_raw;
    const int*       __restrict__ off32 = (const int*)offsets_raw;

    long long start, end;
    if (is64) {
        start = __ldg(&off64[bag]);
        end   = (bag + 1 < num_bags) ? __ldg(&off64[bag + 1]) : total_indices;
    } else {
        start = (long long)__ldg(&off32[bag]);
        end   = (bag + 1 < num_bags) ? (long long)__ldg(&off32[bag + 1]) : total_indices;
    }

    float4 acc = make_float4(0.f, 0.f, 0.f, 0.f);

    long long i = start;
    // Main loop: 4 independent 512B row-pair gathers in flight per warp.
    #pragma unroll 1
    for (; i + 4 <= end; i += 4) {
        unsigned o0, o1, o2, o3;
        if (is64) {
            o0 = (unsigned)ldcs_i64(&idx64[i    ]) << 8;
            o1 = (unsigned)ldcs_i64(&idx64[i + 1]) << 8;
            o2 = (unsigned)ldcs_i64(&idx64[i + 2]) << 8;
            o3 = (unsigned)ldcs_i64(&idx64[i + 3]) << 8;
        } else {
            o0 = (unsigned)ldcs_i32(&idx32[i    ]) << 8;
            o1 = (unsigned)ldcs_i32(&idx32[i + 1]) << 8;
            o2 = (unsigned)ldcs_i32(&idx32[i + 2]) << 8;
            o3 = (unsigned)ldcs_i32(&idx32[i + 3]) << 8;
        }
        float4 v0 = __ldg((const float4*)(wbase + o0));
        float4 v1 = __ldg((const float4*)(wbase + o1));
        float4 v2 = __ldg((const float4*)(wbase + o2));
        float4 v3 = __ldg((const float4*)(wbase + o3));
        acc.x += (v0.x + v1.x) + (v2.x + v3.x);
        acc.y += (v0.y + v1.y) + (v2.y + v3.y);
        acc.z += (v0.z + v1.z) + (v2.z + v3.z);
        acc.w += (v0.w + v1.w) + (v2.w + v3.w);
    }
    // 2-wide tail (covers L % 4 == 2/3 without full serialization).
    if (i + 2 <= end) {
        unsigned o0, o1;
        if (is64) {
            o0 = (unsigned)ldcs_i64(&idx64[i    ]) << 8;
            o1 = (unsigned)ldcs_i64(&idx64[i + 1]) << 8;
        } else {
            o0 = (unsigned)ldcs_i32(&idx32[i    ]) << 8;
            o1 = (unsigned)ldcs_i32(&idx32[i + 1]) << 8;
        }
        float4 v0 = __ldg((const float4*)(wbase + o0));
        float4 v1 = __ldg((const float4*)(wbase + o1));
        acc.x += v0.x + v1.x;
        acc.y += v0.y + v1.y;
        acc.z += v0.z + v1.z;
        acc.w += v0.w + v1.w;
        i += 2;
    }
    if (i < end) {
        unsigned o = (is64 ? (unsigned)ldcs_i64(&idx64[i])
                           : (unsigned)ldcs_i32(&idx32[i])) << 8;
        float4 v = __ldg((const float4*)(wbase + o));
        acc.x += v.x; acc.y += v.y; acc.z += v.z; acc.w += v.w;
    }

    const long long cnt = end - start;
    const float inv = 1.0f / (float)(cnt > 0 ? cnt : 1);
    acc.x *= inv; acc.y *= inv; acc.z *= inv; acc.w *= inv;

    stcs_f4(((float4*)out) + (size_t)bag * 16 + sub, acc);
}

extern "C" void kernel_launch(void* const* d_in, const int* in_sizes, int n_in,
                              void* d_out, int out_size) {
    // metadata order: indices [T], offsets [B], weight [V*D]
    const void* indices = d_in[0];
    const void* offsets = d_in[1];
    const char* weight  = (const char*)d_in[2];
    float*      out     = (float*)d_out;

    const int       num_bags      = in_sizes[1];
    const long long total_indices = in_sizes[0];

    // 2 bags per warp, 8 warps per block -> 16 bags per block.
    const int bags_per_block = 16;
    const int blocks = (num_bags + bags_per_block - 1) / bags_per_block;
    embag_mean_kernel<<<blocks, 256>>>(indices, offsets, weight, out,
                                       num_bags, total_indices);
}

// round 9
// speedup vs baseline: 1.0569x; 1.0569x over previous
#include <cuda_runtime.h>
#include <cstdint>

// embedding_bag(mode='mean'): B bags over a [V,64] fp32 table.
// One HALF-WARP per bag; sublane s (0..15) owns one float4 (cols 4s..4s+3).
// 16 lanes x 16B = one full 256B row per half-warp; each warp LDG.E.128
// fetches TWO rows (512B). Unroll x4 (2KB in flight per warp) + 2-wide tail
// so L=50 (12*4+2) never hits a serialized scalar loop.
// Row addresses are u32 BYTE offsets (V*256B = 256MB fits u32).
// NOTE: no volatile asm in the hot loop (R8 lesson: it blocks ptxas from
// front-batching the index loads). Only the final output store is streaming.

static __device__ __forceinline__ void stcs_f4(float4* p, float4 v) {
    asm volatile("st.global.cs.v4.f32 [%0], {%1,%2,%3,%4};"
                 :: "l"(p), "f"(v.x), "f"(v.y), "f"(v.z), "f"(v.w));
}

__global__ __launch_bounds__(256, 8)
void embag_mean_kernel(const void* __restrict__ indices_raw,
                       const void* __restrict__ offsets_raw,
                       const char* __restrict__ weight_bytes,
                       float* __restrict__ out,
                       int num_bags, long long total_indices) {
    const int warp_global = (int)((blockIdx.x * (unsigned)blockDim.x + threadIdx.x) >> 5);
    const int lane = threadIdx.x & 31;
    const int half = lane >> 4;        // bag within the warp
    const int sub  = lane & 15;        // float4 column group within the row
    const int bag  = 2 * warp_global + half;
    if (bag >= num_bags) return;

    const char* __restrict__ wbase = weight_bytes + (unsigned)(sub * 16);

    // Inline dtype detection (int64 vs int32 indices): ids < 2^31, so an
    // int64 LE buffer has every odd 32-bit word zero; an int32 buffer has
    // random nonzero ids there (P[all 4 zero] ~ 1e-24). Uniform result.
    const int* wprobe = (const int*)indices_raw;
    int allz = 1;
    #pragma unroll
    for (int k = 1; k < 9; k += 2) allz &= (__ldg(&wprobe[k]) == 0);
    const bool is64 = (allz != 0);

    const long long* __restrict__ idx64 = (const long long*)indices_raw;
    const int*       __restrict__ idx32 = (const int*)indices_raw;
    const long long* __restrict__ off64 = (const long long*)offsets_raw;
    const int*       __restrict__ off32 = (const int*)offsets_raw;

    long long start, end;
    if (is64) {
        start = __ldg(&off64[bag]);
        end   = (bag + 1 < num_bags) ? __ldg(&off64[bag + 1]) : total_indices;
    } else {
        start = (long long)__ldg(&off32[bag]);
        end   = (bag + 1 < num_bags) ? (long long)__ldg(&off32[bag + 1]) : total_indices;
    }

    float4 acc = make_float4(0.f, 0.f, 0.f, 0.f);

    long long i = start;
    // Main loop: 4 independent 512B row-pair gathers in flight per warp.
    #pragma unroll 1
    for (; i + 4 <= end; i += 4) {
        unsigned o0, o1, o2, o3;
        if (is64) {
            o0 = (unsigned)__ldg(&idx64[i    ]) << 8;
            o1 = (unsigned)__ldg(&idx64[i + 1]) << 8;
            o2 = (unsigned)__ldg(&idx64[i + 2]) << 8;
            o3 = (unsigned)__ldg(&idx64[i + 3]) << 8;
        } else {
            o0 = (unsigned)__ldg(&idx32[i    ]) << 8;
            o1 = (unsigned)__ldg(&idx32[i + 1]) << 8;
            o2 = (unsigned)__ldg(&idx32[i + 2]) << 8;
            o3 = (unsigned)__ldg(&idx32[i + 3]) << 8;
        }
        float4 v0 = __ldg((const float4*)(wbase + o0));
        float4 v1 = __ldg((const float4*)(wbase + o1));
        float4 v2 = __ldg((const float4*)(wbase + o2));
        float4 v3 = __ldg((const float4*)(wbase + o3));
        acc.x += (v0.x + v1.x) + (v2.x + v3.x);
        acc.y += (v0.y + v1.y) + (v2.y + v3.y);
        acc.z += (v0.z + v1.z) + (v2.z + v3.z);
        acc.w += (v0.w + v1.w) + (v2.w + v3.w);
    }
    // 2-wide tail (covers L % 4 == 2/3 without full serialization).
    if (i + 2 <= end) {
        unsigned o0, o1;
        if (is64) {
            o0 = (unsigned)__ldg(&idx64[i    ]) << 8;
            o1 = (unsigned)__ldg(&idx64[i + 1]) << 8;
        } else {
            o0 = (unsigned)__ldg(&idx32[i    ]) << 8;
            o1 = (unsigned)__ldg(&idx32[i + 1]) << 8;
        }
        float4 v0 = __ldg((const float4*)(wbase + o0));
        float4 v1 = __ldg((const float4*)(wbase + o1));
        acc.x += v0.x + v1.x;
        acc.y += v0.y + v1.y;
        acc.z += v0.z + v1.z;
        acc.w += v0.w + v1.w;
        i += 2;
    }
    if (i < end) {
        unsigned o = (is64 ? (unsigned)__ldg(&idx64[i])
                           : (unsigned)__ldg(&idx32[i])) << 8;
        float4 v = __ldg((const float4*)(wbase + o));
        acc.x += v.x; acc.y += v.y; acc.z += v.z; acc.w += v.w;
    }

    const long long cnt = end - start;
    const float inv = 1.0f / (float)(cnt > 0 ? cnt : 1);
    acc.x *= inv; acc.y *= inv; acc.z *= inv; acc.w *= inv;

    stcs_f4(((float4*)out) + (size_t)bag * 16 + sub, acc);
}

extern "C" void kernel_launch(void* const* d_in, const int* in_sizes, int n_in,
                              void* d_out, int out_size) {
    // metadata order: indices [T], offsets [B], weight [V*D]
    const void* indices = d_in[0];
    const void* offsets = d_in[1];
    const char* weight  = (const char*)d_in[2];
    float*      out     = (float*)d_out;

    const int       num_bags      = in_sizes[1];
    const long long total_indices = in_sizes[0];

    // 2 bags per warp, 8 warps per block -> 16 bags per block.
    const int bags_per_block = 16;
    const int blocks = (num_bags + bags_per_block - 1) / bags_per_block;
    embag_mean_kernel<<<blocks, 256>>>(indices, offsets, weight, out,
                                       num_bags, total_indices);
}

// round 10
// speedup vs baseline: 1.0667x; 1.0092x over previous
#include <cuda_runtime.h>
#include <cstdint>

// embedding_bag(mode='mean'): B bags over a [V,64] fp32 table.
// One HALF-WARP per bag; sublane s (0..15) owns one float4 (cols 4s..4s+3).
// 16 lanes x 16B = one full 256B row per half-warp; each warp LDG.E.128
// fetches TWO rows (512B). Unroll x4 (2KB in flight per warp) + 2-wide tail
// so L=50 (12*4+2) never hits a serialized scalar loop.
// Row addresses are u32 BYTE offsets (V*256B = 256MB fits u32).
// Cache policy (intrinsics only — R8 lesson: asm volatile in the hot loop
// blocks ptxas index-load batching):
//   - weight gathers: __ldcg (L2-only; L1 hit rate is ~0% on a 143MB random
//     footprint, so L1 fills are pure overhead)
//   - output: __stcs (write-once streaming)
//   - indices/offsets: __ldg (small, read-once, front-batched by ptxas)

__global__ __launch_bounds__(256, 8)
void embag_mean_kernel(const void* __restrict__ indices_raw,
                       const void* __restrict__ offsets_raw,
                       const char* __restrict__ weight_bytes,
                       float* __restrict__ out,
                       int num_bags, long long total_indices) {
    const int warp_global = (int)((blockIdx.x * (unsigned)blockDim.x + threadIdx.x) >> 5);
    const int lane = threadIdx.x & 31;
    const int half = lane >> 4;        // bag within the warp
    const int sub  = lane & 15;        // float4 column group within the row
    const int bag  = 2 * warp_global + half;
    if (bag >= num_bags) return;

    const char* __restrict__ wbase = weight_bytes + (unsigned)(sub * 16);

    // Inline dtype detection (int64 vs int32 indices): ids < 2^31, so an
    // int64 LE buffer has every odd 32-bit word zero; an int32 buffer has
    // random nonzero ids there (P[all 4 zero] ~ 1e-24). Uniform result.
    const int* wprobe = (const int*)indices_raw;
    int allz = 1;
    #pragma unroll
    for (int k = 1; k < 9; k += 2) allz &= (__ldg(&wprobe[k]) == 0);
    const bool is64 = (allz != 0);

    const long long* __restrict__ idx64 = (const long long*)indices_raw;
    const int*       __restrict__ idx32 = (const int*)indices_raw;
    const long long* __restrict__ off64 = (const long long*)offsets_raw;
    const int*       __restrict__ off32 = (const int*)offsets_raw;

    long long start, end;
    if (is64) {
        start = __ldg(&off64[bag]);
        end   = (bag + 1 < num_bags) ? __ldg(&off64[bag + 1]) : total_indices;
    } else {
        start = (long long)__ldg(&off32[bag]);
        end   = (bag + 1 < num_bags) ? (long long)__ldg(&off32[bag + 1]) : total_indices;
    }

    float4 acc = make_float4(0.f, 0.f, 0.f, 0.f);

    long long i = start;
    // Main loop: 4 independent 512B row-pair gathers in flight per warp.
    #pragma unroll 1
    for (; i + 4 <= end; i += 4) {
        unsigned o0, o1, o2, o3;
        if (is64) {
            o0 = (unsigned)__ldg(&idx64[i    ]) << 8;
            o1 = (unsigned)__ldg(&idx64[i + 1]) << 8;
            o2 = (unsigned)__ldg(&idx64[i + 2]) << 8;
            o3 = (unsigned)__ldg(&idx64[i + 3]) << 8;
        } else {
            o0 = (unsigned)__ldg(&idx32[i    ]) << 8;
            o1 = (unsigned)__ldg(&idx32[i + 1]) << 8;
            o2 = (unsigned)__ldg(&idx32[i + 2]) << 8;
            o3 = (unsigned)__ldg(&idx32[i + 3]) << 8;
        }
        float4 v0 = __ldcg((const float4*)(wbase + o0));
        float4 v1 = __ldcg((const float4*)(wbase + o1));
        float4 v2 = __ldcg((const float4*)(wbase + o2));
        float4 v3 = __ldcg((const float4*)(wbase + o3));
        acc.x += (v0.x + v1.x) + (v2.x + v3.x);
        acc.y += (v0.y + v1.y) + (v2.y + v3.y);
        acc.z += (v0.z + v1.z) + (v2.z + v3.z);
        acc.w += (v0.w + v1.w) + (v2.w + v3.w);
    }
    // 2-wide tail (covers L % 4 == 2/3 without full serialization).
    if (i + 2 <= end) {
        unsigned o0, o1;
        if (is64) {
            o0 = (unsigned)__ldg(&idx64[i    ]) << 8;
            o1 = (unsigned)__ldg(&idx64[i + 1]) << 8;
        } else {
            o0 = (unsigned)__ldg(&idx32[i    ]) << 8;
            o1 = (unsigned)__ldg(&idx32[i + 1]) << 8;
        }
        float4 v0 = __ldcg((const float4*)(wbase + o0));
        float4 v1 = __ldcg((const float4*)(wbase + o1));
        acc.x += v0.x + v1.x;
        acc.y += v0.y + v1.y;
        acc.z += v0.z + v1.z;
        acc.w += v0.w + v1.w;
        i += 2;
    }
    if (i < end) {
        unsigned o = (is64 ? (unsigned)__ldg(&idx64[i])
                           : (unsigned)__ldg(&idx32[i])) << 8;
        float4 v = __ldcg((const float4*)(wbase + o));
        acc.x += v.x; acc.y += v.y; acc.z += v.z; acc.w += v.w;
    }

    const long long cnt = end - start;
    const float inv = 1.0f / (float)(cnt > 0 ? cnt : 1);
    acc.x *= inv; acc.y *= inv; acc.z *= inv; acc.w *= inv;

    __stcs(((float4*)out) + (size_t)bag * 16 + sub, acc);
}

extern "C" void kernel_launch(void* const* d_in, const int* in_sizes, int n_in,
                              void* d_out, int out_size) {
    // metadata order: indices [T], offsets [B], weight [V*D]
    const void* indices = d_in[0];
    const void* offsets = d_in[1];
    const char* weight  = (const char*)d_in[2];
    float*      out     = (float*)d_out;

    const int       num_bags      = in_sizes[1];
    const long long total_indices = in_sizes[0];

    // 2 bags per warp, 8 warps per block -> 16 bags per block.
    const int bags_per_block = 16;
    const int blocks = (num_bags + bags_per_block - 1) / bags_per_block;
    embag_mean_kernel<<<blocks, 256>>>(indices, offsets, weight, out,
                                       num_bags, total_indices);
}